// round 16
// baseline (speedup 1.0000x reference)
#include <cuda_runtime.h>

#define B_   2
#define LSEQ 768
#define SIN  1280
#define SOUT 32
#define ZF   32
#define DI   64
#define DS   16
#define NCH  192    // sub-chunks along L (within batch)
#define CT   4      // sub-chunk length
#define NROWS (B_*LSEQ)          // 1536
#define CHAINS (B_*DI*DS)        // 2048
#define NBLK 128
#define UNITS 3
#define BLKB  64    // blocks per batch
#define NKT  (SIN/32)            // 40 k-tiles

// ---------------- scratch -----------------------------------------------
__device__ float g_x[NROWS*DI];
__device__ float g_gate[NROWS*DI];
__device__ float g_dt[NROWS*DI];
__device__ float g_Bm[NROWS*DS];
__device__ float g_Cm[NROWS*DS];
__device__ float g_ca[NCH*CHAINS];         // sub-chunk summaries
__device__ float g_cb[NCH*CHAINS];
__device__ float g_ba[BLKB*CHAINS];        // block-level (12-row) summaries
__device__ float g_bb[BLKB*CHAINS];

// ---------------- software grid barrier (128 blocks, all resident) --------
__device__ unsigned g_bar_count = 0;
__device__ volatile unsigned g_bar_gen = 0;

__device__ __forceinline__ void grid_barrier() {
    __syncthreads();
    if (threadIdx.x == 0) {
        __threadfence();
        unsigned gen = g_bar_gen;
        if (atomicAdd(&g_bar_count, 1u) == NBLK - 1u) {
            g_bar_count = 0;
            __threadfence();
            g_bar_gen = gen + 1;
        } else {
            while (g_bar_gen == gen) { }
            __threadfence();
        }
    }
    __syncthreads();
}

// ---------------- shared-memory phase union --------------------------------
struct PhaseB { float sxpre[7][64]; float sx[4][64];
                float xd[4][34]; float sdt[4][64]; };
struct PhaseC { float sx[4][64]; float sg[4][64]; float sdt[4][64];
                float sB[4][16]; float sC[4][16]; float ysm[4][64]; };
union SmemU {
    struct { float wdup[32][64]; float sT[UNITS][32][8]; } ab;   // 11 KB
    struct { PhaseB b[UNITS]; float winw[128][33]; float scwT[4][64];
             float scb[64]; float sdtw[128]; float sdtb[64]; } pb;
    struct { PhaseC c[UNITS]; float sop[32][65]; } pc;
};

// ---------------- mamba_one: s' pipeline (fused AB, C) ---------------------
// grid = 128 blocks x 768 threads; block = 3 units of 256 threads = 12 rows.
__global__ void __launch_bounds__(768) mamba_one(
    const float* __restrict__ s,    const float* __restrict__ spw,
    const float* __restrict__ spb,  const float* __restrict__ inw,
    const float* __restrict__ convw,const float* __restrict__ convb,
    const float* __restrict__ xpw,  const float* __restrict__ dtw,
    const float* __restrict__ dtb,  const float* __restrict__ A_log,
    const float* __restrict__ Dp,   const float* __restrict__ opw,
    float* __restrict__ out)
{
    __shared__ SmemU un;
    __shared__ __align__(16) float sps_s[UNITS][8][33];  // s' rows base-3..base+4
    __shared__ __align__(16) float s_exA[1024];
    __shared__ __align__(16) float s_exB[1024];
    int tid  = threadIdx.x;
    int u    = tid >> 8;            // 0..2
    int utid = tid & 255;

    int cu   = blockIdx.x * UNITS + u;      // sub-chunk 0..383
    int base = cu * 4;
    int b    = base / LSEQ;
    int l0   = base % LSEQ;
    int c    = l0 >> 2;                     // 0..191 within batch
    int blk  = blockIdx.x % BLKB;

    // =================== phase AB-1: s' rows (redundant direct GEMM) =======
    // outputs: 8 rows (base-3..base+4) x 32 cols, full K=1280.
    {
        int ph = (utid >> 5) & 1;           // row-quad for compute threads
        int j  = utid & 31;
        unsigned long long acc0 = 0ull, acc1 = 0ull;
        int srow = utid & 7;                // staging row
        int skk  = utid >> 3;               // staging k (0..31)
        int grow = base - 3 + srow;
        if (grow < 0) grow = 0;
        if (grow >= NROWS) grow = NROWS - 1;
        const float* srcrow = s + (size_t)grow * SIN;
        int wj  = tid >> 4;                 // 0..47 (<32 used)
        int wk2 = (tid & 15) * 2;

        #pragma unroll 1
        for (int tile = 0; tile < NKT; tile++) {
            int ktb = tile * 32;
            __syncthreads();
            if (tid < 512) {                // stage weights duplicated (block)
                float2 w = *(const float2*)(spw + (size_t)wj * SIN + ktb + wk2);
                un.ab.wdup[wk2 + 0][2 * wj] = w.x; un.ab.wdup[wk2 + 0][2 * wj + 1] = w.x;
                un.ab.wdup[wk2 + 1][2 * wj] = w.y; un.ab.wdup[wk2 + 1][2 * wj + 1] = w.y;
            }
            un.ab.sT[u][skk][srow] = srcrow[ktb + skk];   // stage s (per unit)
            __syncthreads();
            if (utid < 64) {
                #pragma unroll
                for (int k = 0; k < 32; k++) {
                    ulonglong2 sp2 = *(const ulonglong2*)&un.ab.sT[u][k][4 * ph];
                    unsigned long long wv = *(const unsigned long long*)&un.ab.wdup[k][2 * j];
                    asm("fma.rn.f32x2 %0, %1, %2, %0;" : "+l"(acc0) : "l"(sp2.x), "l"(wv));
                    asm("fma.rn.f32x2 %0, %1, %2, %0;" : "+l"(acc1) : "l"(sp2.y), "l"(wv));
                }
            }
        }
        if (utid < 64) {
            float2 q0 = *(float2*)&acc0, q1 = *(float2*)&acc1;
            float bias = spb[j];
            float vals[4] = {q0.x, q0.y, q1.x, q1.y};
            #pragma unroll
            for (int r = 0; r < 4; r++) {
                int lr = 4 * ph + r;
                float v = vals[r] + bias;
                if (l0 == 0 && lr < 3) v = 0.f;   // zero halo at batch start
                sps_s[u][lr][j] = v;
            }
        }
    }
    __syncthreads();

    // =================== phase AB-2: in_proj + conv + x_proj + dt ==========
    {
        PhaseB& Bv = un.pb.b[u];

        for (int idx = tid; idx < 128 * 32; idx += 768)
            un.pb.winw[idx >> 5][idx & 31] = inw[idx];
        if (tid < 256)        un.pb.scwT[tid & 3][tid >> 2] = convw[tid];
        else if (tid < 320)   un.pb.scb[tid - 256] = convb[tid - 256];
        else if (tid < 448)   un.pb.sdtw[tid - 320] = dtw[tid - 320];
        else if (tid < 512)   un.pb.sdtb[tid - 448] = dtb[tid - 448];
        __syncthreads();

        for (int idx = utid; idx < 7 * 64 + 4 * 64; idx += 256) {
            if (idx < 7 * 64) {
                int row = idx >> 6, d = idx & 63;
                float a = 0.f;
                #pragma unroll
                for (int k = 0; k < 32; k++) a = fmaf(sps_s[u][row][k], un.pb.winw[d][k], a);
                Bv.sxpre[row][d] = a;
            } else {
                int i2 = idx - 7 * 64;
                int row = i2 >> 6, d = i2 & 63;
                float a = 0.f;
                #pragma unroll
                for (int k = 0; k < 32; k++) a = fmaf(sps_s[u][row + 3][k], un.pb.winw[64 + d][k], a);
                g_gate[(base + row) * DI + d] = a;
            }
        }
        __syncthreads();

        {   // conv + silu: 4 rows x 64 = 256
            int r = utid >> 6, d = utid & 63;
            float acc = un.pb.scb[d];
            #pragma unroll
            for (int kk = 0; kk < 4; kk++)
                acc = fmaf(Bv.sxpre[r + kk][d], un.pb.scwT[kk][d], acc);
            float xv = acc / (1.f + __expf(-acc));
            Bv.sx[r][d] = xv;
            g_x[(base + r) * DI + d] = xv;
        }
        __syncthreads();

        if (utid < 136) {                       // x_proj: 4 rows x 34
            int r = utid / 34, jj = utid % 34;
            float a = 0.f;
            #pragma unroll
            for (int dd = 0; dd < 64; dd++) a = fmaf(Bv.sx[r][dd], xpw[jj * 64 + dd], a);
            Bv.xd[r][jj] = a;
            if (jj >= 18)      g_Cm[(base + r) * DS + (jj - 18)] = a;
            else if (jj >= 2)  g_Bm[(base + r) * DS + (jj - 2)]  = a;
        }
        __syncthreads();

        {   // dt = softplus(...): 256
            int r = utid >> 6, d = utid & 63;
            float dtraw = fmaf(Bv.xd[r][0], un.pb.sdtw[d * 2],
                          fmaf(Bv.xd[r][1], un.pb.sdtw[d * 2 + 1], un.pb.sdtb[d]));
            float dtv = fmaxf(dtraw, 0.f) + log1pf(__expf(-fabsf(dtraw)));
            Bv.sdt[r][d] = dtv;
            g_dt[(base + r) * DI + d] = dtv;
        }
        __syncthreads();

        // sub-chunk summaries (4 chains/thread) + 3-unit block summary
        {
            int d = utid >> 2;
            int n0 = (utid & 3) * 4;
            float4 al = *(const float4*)(A_log + d * DS + n0);
            float a0 = -__expf(al.x), a1 = -__expf(al.y);
            float a2 = -__expf(al.z), a3 = -__expf(al.w);
            float ra0 = 1.f, ra1 = 1.f, ra2 = 1.f, ra3 = 1.f;
            float rb0 = 0.f, rb1 = 0.f, rb2 = 0.f, rb3 = 0.f;
            #pragma unroll
            for (int t = 0; t < CT; t++) {
                float dtv = Bv.sdt[t][d];
                float dtx = dtv * Bv.sx[t][d];
                float dA0 = __expf(dtv * a0), dA1 = __expf(dtv * a1);
                float dA2 = __expf(dtv * a2), dA3 = __expf(dtv * a3);
                ra0 *= dA0; ra1 *= dA1; ra2 *= dA2; ra3 *= dA3;
                rb0 = fmaf(dA0, rb0, dtx * Bv.xd[t][2 + n0]);
                rb1 = fmaf(dA1, rb1, dtx * Bv.xd[t][3 + n0]);
                rb2 = fmaf(dA2, rb2, dtx * Bv.xd[t][4 + n0]);
                rb3 = fmaf(dA3, rb3, dtx * Bv.xd[t][5 + n0]);
            }
            size_t o = (size_t)c * CHAINS + b * 1024 + 4 * utid;
            *(float4*)(g_ca + o) = make_float4(ra0, ra1, ra2, ra3);
            *(float4*)(g_cb + o) = make_float4(rb0, rb1, rb2, rb3);

            // serial 3-unit combine -> block summary
            if (u == 0) {
                *(float4*)(s_exA + 4 * utid) = make_float4(ra0, ra1, ra2, ra3);
                *(float4*)(s_exB + 4 * utid) = make_float4(rb0, rb1, rb2, rb3);
            }
            __syncthreads();
            if (u == 1) {
                float4 pa = *(const float4*)(s_exA + 4 * utid);
                float4 pb = *(const float4*)(s_exB + 4 * utid);
                float4 NA, NB;
                NA.x = ra0 * pa.x;  NB.x = fmaf(ra0, pb.x, rb0);
                NA.y = ra1 * pa.y;  NB.y = fmaf(ra1, pb.y, rb1);
                NA.z = ra2 * pa.z;  NB.z = fmaf(ra2, pb.z, rb2);
                NA.w = ra3 * pa.w;  NB.w = fmaf(ra3, pb.w, rb3);
                *(float4*)(s_exA + 4 * utid) = NA;
                *(float4*)(s_exB + 4 * utid) = NB;
            }
            __syncthreads();
            if (u == 2) {
                float4 pa = *(const float4*)(s_exA + 4 * utid);
                float4 pb = *(const float4*)(s_exB + 4 * utid);
                float4 NA, NB;
                NA.x = ra0 * pa.x;  NB.x = fmaf(ra0, pb.x, rb0);
                NA.y = ra1 * pa.y;  NB.y = fmaf(ra1, pb.y, rb1);
                NA.z = ra2 * pa.z;  NB.z = fmaf(ra2, pb.z, rb2);
                NA.w = ra3 * pa.w;  NB.w = fmaf(ra3, pb.w, rb3);
                size_t ob = (size_t)blk * CHAINS + b * 1024 + 4 * utid;
                *(float4*)(g_ba + ob) = NA;
                *(float4*)(g_bb + ob) = NB;
            }
        }
    }
    grid_barrier();   // (only barrier): all ca/cb/ba/bb + g_x/g_gate/g_dt visible

    // =================== phase C: 2-level prefix + scan + gate + out_proj ==
    {
        PhaseC& C = un.pc.c[u];

        for (int idx = tid; idx < 2048; idx += 768)
            un.pc.sop[idx >> 6][idx & 63] = opw[idx];
        {
            int t = utid >> 6, dd = utid & 63;
            C.sx[t][dd]  = g_x[(base + t) * DI + dd];
            C.sg[t][dd]  = g_gate[(base + t) * DI + dd];
            C.sdt[t][dd] = g_dt[(base + t) * DI + dd];
        }
        if (utid < 64) {
            int t = utid >> 4, nn = utid & 15;
            C.sB[t][nn] = g_Bm[(base + t) * DS + nn];
            C.sC[t][nn] = g_Cm[(base + t) * DS + nn];
        }

        int d = utid >> 2;
        int n0 = (utid & 3) * 4;
        float4 al = *(const float4*)(A_log + 4 * utid);
        float a0 = -__expf(al.x), a1 = -__expf(al.y);
        float a2 = -__expf(al.z), a3 = -__expf(al.w);
        float h0 = 0.f, h1 = 0.f, h2 = 0.f, h3 = 0.f;
        {
            size_t gc = (size_t)b * 1024 + 4 * utid;
            #pragma unroll 4
            for (int bk = 0; bk < blk; bk++) {
                float4 av = *(const float4*)(g_ba + (size_t)bk * CHAINS + gc);
                float4 bv = *(const float4*)(g_bb + (size_t)bk * CHAINS + gc);
                h0 = fmaf(av.x, h0, bv.x);
                h1 = fmaf(av.y, h1, bv.y);
                h2 = fmaf(av.z, h2, bv.z);
                h3 = fmaf(av.w, h3, bv.w);
            }
            for (int cc2 = blk * UNITS; cc2 < c; cc2++) {
                float4 av = *(const float4*)(g_ca + (size_t)cc2 * CHAINS + gc);
                float4 bv = *(const float4*)(g_cb + (size_t)cc2 * CHAINS + gc);
                h0 = fmaf(av.x, h0, bv.x);
                h1 = fmaf(av.y, h1, bv.y);
                h2 = fmaf(av.z, h2, bv.z);
                h3 = fmaf(av.w, h3, bv.w);
            }
        }
        float Dv = Dp[d];
        __syncthreads();

        #pragma unroll
        for (int t = 0; t < CT; t++) {
            float dtv = C.sdt[t][d];
            float xv  = C.sx[t][d];
            float dtx = dtv * xv;
            float dA0 = __expf(dtv * a0), dA1 = __expf(dtv * a1);
            float dA2 = __expf(dtv * a2), dA3 = __expf(dtv * a3);
            h0 = fmaf(dA0, h0, dtx * C.sB[t][n0 + 0]);
            h1 = fmaf(dA1, h1, dtx * C.sB[t][n0 + 1]);
            h2 = fmaf(dA2, h2, dtx * C.sB[t][n0 + 2]);
            h3 = fmaf(dA3, h3, dtx * C.sB[t][n0 + 3]);
            float yp = h0 * C.sC[t][n0 + 0] + h1 * C.sC[t][n0 + 1]
                     + h2 * C.sC[t][n0 + 2] + h3 * C.sC[t][n0 + 3];
            yp += __shfl_xor_sync(0xffffffffu, yp, 1);
            yp += __shfl_xor_sync(0xffffffffu, yp, 2);
            if ((utid & 3) == 0) {
                float y = yp + xv * Dv;
                float g = C.sg[t][d];
                y *= g / (1.f + __expf(-g));
                C.ysm[t][d] = y;
            }
        }
        __syncthreads();
        if (utid < CT * SOUT) {                 // 128 threads: 4 t x 32 f
            int t = utid >> 5, f = utid & 31;
            float acc = 0.f;
            #pragma unroll
            for (int dd = 0; dd < DI; dd++)
                acc = fmaf(C.ysm[t][dd], un.pc.sop[f][dd], acc);
            out[(size_t)(base + t) * SOUT + f] = acc;
        }
    }
}

// ---------------- K7: z_prime = z*zw + zb + outer(sp, sp) ------------------
// grid = B_ x 192 s-groups(4 rows) x 12 t-strips(64 t) = 4608 blocks; block 256.
__global__ void __launch_bounds__(256) k7_z(const float* __restrict__ z,
                                            const float* __restrict__ zw,
                                            const float* __restrict__ zbv,
                                            const float* __restrict__ sp,
                                            float* __restrict__ outz) {
    int blk = blockIdx.x;
    int b = blk / 2304;
    int rem = blk % 2304;
    int s0 = (rem / 12) * 4;
    int t0 = (rem % 12) * 64;
    int tx = threadIdx.x & 7;
    int tl = threadIdx.x >> 3;
    int tb = t0 + tl * 2;
    const float* zrow = z + (size_t)(b * LSEQ) * LSEQ;
    float* orow = outz + (size_t)(b * LSEQ) * LSEQ * ZF;

    float2 zq[4];
    #pragma unroll
    for (int si = 0; si < 4; si++)
        zq[si] = *(const float2*)(zrow + (size_t)(s0 + si) * LSEQ + tb);
    float4 sps[4];
    #pragma unroll
    for (int si = 0; si < 4; si++)
        sps[si] = ((const float4*)(sp + (size_t)(b * LSEQ + s0 + si) * SOUT))[tx];
    float4 spt0 = ((const float4*)(sp + (size_t)(b * LSEQ + tb) * SOUT))[tx];
    float4 spt1 = ((const float4*)(sp + (size_t)(b * LSEQ + tb + 1) * SOUT))[tx];
    float4 zw4 = ((const float4*)zw)[tx];
    float4 zb4 = ((const float4*)zbv)[tx];

    #pragma unroll
    for (int si = 0; si < 4; si++) {
        float zv0 = zq[si].x, zv1 = zq[si].y;
        float4 o0, o1;
        o0.x = fmaf(zv0, zw4.x, zb4.x) + sps[si].x * spt0.x;
        o0.y = fmaf(zv0, zw4.y, zb4.y) + sps[si].y * spt0.y;
        o0.z = fmaf(zv0, zw4.z, zb4.z) + sps[si].z * spt0.z;
        o0.w = fmaf(zv0, zw4.w, zb4.w) + sps[si].w * spt0.w;
        o1.x = fmaf(zv1, zw4.x, zb4.x) + sps[si].x * spt1.x;
        o1.y = fmaf(zv1, zw4.y, zb4.y) + sps[si].y * spt1.y;
        o1.z = fmaf(zv1, zw4.z, zb4.z) + sps[si].z * spt1.z;
        o1.w = fmaf(zv1, zw4.w, zb4.w) + sps[si].w * spt1.w;
        size_t rb_ = (size_t)(s0 + si) * LSEQ + tb;
        __stcs((float4*)(orow + rb_ * ZF + tx * 4), o0);
        __stcs((float4*)(orow + (rb_ + 1) * ZF + tx * 4), o1);
    }
}

// ---------------- launch ----------------------------------------------------
extern "C" void kernel_launch(void* const* d_in, const int* in_sizes, int n_in,
                              void* d_out, int out_size) {
    const float* s        = (const float*)d_in[0];
    const float* z        = (const float*)d_in[1];
    const float* s_proj_w = (const float*)d_in[2];
    const float* s_proj_b = (const float*)d_in[3];
    const float* z_proj_w = (const float*)d_in[4];
    const float* z_proj_b = (const float*)d_in[5];
    const float* in_proj_w= (const float*)d_in[6];
    const float* conv_w   = (const float*)d_in[7];
    const float* conv_b   = (const float*)d_in[8];
    const float* x_proj_w = (const float*)d_in[9];
    const float* dt_proj_w= (const float*)d_in[10];
    const float* dt_proj_b= (const float*)d_in[11];
    const float* A_log    = (const float*)d_in[12];
    const float* Dp       = (const float*)d_in[13];
    const float* out_proj_w = (const float*)d_in[14];

    float* out    = (float*)d_out;
    float* sp_out = out;                       // [2,768,32]
    float* z_out  = out + (size_t)B_ * LSEQ * SOUT;

    mamba_one<<<NBLK, 768>>>(s, s_proj_w, s_proj_b, in_proj_w, conv_w, conv_b,
                             x_proj_w, dt_proj_w, dt_proj_b, A_log, Dp,
                             out_proj_w, sp_out);
    k7_z<<<4608, 256>>>(z, z_proj_w, z_proj_b, sp_out, z_out);
}

// round 17
// speedup vs baseline: 1.5191x; 1.5191x over previous
#include <cuda_runtime.h>

#define B_   2
#define LSEQ 768
#define SIN  1280
#define SOUT 32
#define ZF   32
#define DI   64
#define DS   16
#define NCH  192    // sub-chunks along L (within batch)
#define CT   4      // sub-chunk length
#define NROWS (B_*LSEQ)          // 1536
#define CHAINS (B_*DI*DS)        // 2048
#define KSP  16     // split-K for phase A
#define KCA  (SIN/KSP)           // 80
#define KT   16     // k sub-tile
#define NBLK 128
#define UNITS 3
#define BLKB  64    // blocks per batch

// ---------------- scratch -----------------------------------------------
__device__ float g_part[KSP*NROWS*SOUT];   // phase-A partials (3 MB)
__device__ float g_x[NROWS*DI];
__device__ float g_gate[NROWS*DI];
__device__ float g_dt[NROWS*DI];
__device__ float g_Bm[NROWS*DS];
__device__ float g_Cm[NROWS*DS];
__device__ float g_ca[NCH*CHAINS];         // sub-chunk summaries
__device__ float g_cb[NCH*CHAINS];
__device__ float g_ba[BLKB*CHAINS];        // block-level (12-row) summaries
__device__ float g_bb[BLKB*CHAINS];

// ---------------- software grid barrier (128 blocks, all resident) --------
__device__ unsigned g_bar_count = 0;
__device__ volatile unsigned g_bar_gen = 0;

__device__ __forceinline__ void grid_barrier() {
    __syncthreads();
    if (threadIdx.x == 0) {
        __threadfence();
        unsigned gen = g_bar_gen;
        if (atomicAdd(&g_bar_count, 1u) == NBLK - 1u) {
            g_bar_count = 0;
            __threadfence();
            g_bar_gen = gen + 1;
        } else {
            while (g_bar_gen == gen) { }
            __threadfence();
        }
    }
    __syncthreads();
}

// per-unit named barrier: 256 threads of unit u
__device__ __forceinline__ void unit_bar(int u) {
    asm volatile("bar.sync %0, 256;" :: "r"(u + 1) : "memory");
}

// ---------------- shared-memory phase union --------------------------------
struct PhaseA { float sT[KT][68]; float wdup[KT][64]; };
struct PhaseB { float sps[7][33]; float sxpre[7][64]; float sx[4][64];
                float xd[4][34]; float sdt[4][64]; };
struct PhaseC { float sx[4][64]; float sg[4][64]; float sdt[4][64];
                float sB[4][16]; float sC[4][16]; float ysm[4][64]; };
union SmemU {
    PhaseA a[UNITS];
    struct { PhaseB b[UNITS]; float winw[128][33]; float scwT[4][64];
             float scb[64]; float sdtw[128]; float sdtb[64]; } pb;
    struct { PhaseC c[UNITS]; float sop[32][65]; } pc;
};

// ---------------- mamba_one: s' pipeline (phases A,B,C) --------------------
// grid = 128 blocks x 768 threads; block = 3 units of 256 threads = 12 rows.
__global__ void __launch_bounds__(768) mamba_one(
    const float* __restrict__ s,    const float* __restrict__ spw,
    const float* __restrict__ spb,  const float* __restrict__ inw,
    const float* __restrict__ convw,const float* __restrict__ convb,
    const float* __restrict__ xpw,  const float* __restrict__ dtw,
    const float* __restrict__ dtb,  const float* __restrict__ A_log,
    const float* __restrict__ Dp,   const float* __restrict__ opw,
    float* __restrict__ out)
{
    __shared__ SmemU un;
    __shared__ __align__(16) float s_exA[1024];
    __shared__ __align__(16) float s_exB[1024];
    int tid  = threadIdx.x;
    int u    = tid >> 8;            // 0..2
    int utid = tid & 255;

    // =================== phase A: s' partials (split-K GEMM) ===============
    // per-unit staging + per-unit named barriers (units drift independently)
    {
        PhaseA& A = un.a[u];
        int unit = blockIdx.x * UNITS + u;      // 0..383
        int rt = unit >> 4, ks = unit & 15;
        int r0 = rt * 64, kb = ks * KCA;
        int j  = utid & 31;
        int pg = utid >> 5;                     // 0..7 -> rows pg*8..+7
        unsigned long long acc[4] = {0ull, 0ull, 0ull, 0ull};
        int lrow = utid >> 2, lk4 = (utid & 3) * 4;    // sT staging
        int wj   = utid >> 3, wk2 = (utid & 7) * 2;    // w staging

        #pragma unroll 1
        for (int tile = 0; tile < KCA / KT; tile++) {
            int ktb = kb + tile * KT;
            unit_bar(u);
            {   // stage s transposed: 64 rows x 16 k
                float4 v = *(const float4*)(s + (size_t)(r0 + lrow) * SIN + ktb + lk4);
                A.sT[lk4 + 0][lrow] = v.x; A.sT[lk4 + 1][lrow] = v.y;
                A.sT[lk4 + 2][lrow] = v.z; A.sT[lk4 + 3][lrow] = v.w;
            }
            {   // stage weights duplicated: 32 cols x 16 k
                float2 w = *(const float2*)(spw + (size_t)wj * SIN + ktb + wk2);
                A.wdup[wk2 + 0][2 * wj] = w.x; A.wdup[wk2 + 0][2 * wj + 1] = w.x;
                A.wdup[wk2 + 1][2 * wj] = w.y; A.wdup[wk2 + 1][2 * wj + 1] = w.y;
            }
            unit_bar(u);
            #pragma unroll
            for (int k = 0; k < KT; k++) {
                ulonglong2 pA = *(const ulonglong2*)&A.sT[k][pg * 8];
                ulonglong2 pB = *(const ulonglong2*)&A.sT[k][pg * 8 + 4];
                unsigned long long wv = *(const unsigned long long*)&A.wdup[k][2 * j];
                asm("fma.rn.f32x2 %0, %1, %2, %0;" : "+l"(acc[0]) : "l"(pA.x), "l"(wv));
                asm("fma.rn.f32x2 %0, %1, %2, %0;" : "+l"(acc[1]) : "l"(pA.y), "l"(wv));
                asm("fma.rn.f32x2 %0, %1, %2, %0;" : "+l"(acc[2]) : "l"(pB.x), "l"(wv));
                asm("fma.rn.f32x2 %0, %1, %2, %0;" : "+l"(acc[3]) : "l"(pB.y), "l"(wv));
            }
        }
        #pragma unroll
        for (int q = 0; q < 4; q++) {
            float2 v = *(float2*)&acc[q];
            int row = r0 + pg * 8 + q * 2;
            g_part[(size_t)ks * NROWS * SOUT + (size_t)row * SOUT + j]       = v.x;
            g_part[(size_t)ks * NROWS * SOUT + (size_t)(row + 1) * SOUT + j] = v.y;
        }
    }
    __syncthreads();  // re-converge before smem union is re-purposed
    grid_barrier();   // #1: all partials visible

    // =================== phase B: reduce + in_proj + conv + x_proj + dt ====
    {
        PhaseB& Bv = un.pb.b[u];
        int cu = blockIdx.x * UNITS + u;        // sub-chunk 0..383
        int base = cu * 4;
        int b = base / LSEQ;
        int l0 = base % LSEQ;
        int c = l0 >> 2;                        // 0..191 within batch

        for (int idx = tid; idx < 128 * 32; idx += 768)
            un.pb.winw[idx >> 5][idx & 31] = inw[idx];
        if (tid < 256)        un.pb.scwT[tid & 3][tid >> 2] = convw[tid];
        else if (tid < 320)   un.pb.scb[tid - 256] = convb[tid - 256];
        else if (tid < 448)   un.pb.sdtw[tid - 320] = dtw[tid - 320];
        else if (tid < 512)   un.pb.sdtb[tid - 448] = dtb[tid - 448];

        if (utid < 7 * SOUT) {                  // reduce partials + bias -> s'
            int row = utid >> 5, jj = utid & 31;
            int grow = base + row - 3;
            float v = 0.f;
            if (l0 != 0 || row >= 3) {
                v = spb[jj];
                #pragma unroll
                for (int ks = 0; ks < KSP; ks++)
                    v += g_part[(size_t)ks * NROWS * SOUT + (size_t)grow * SOUT + jj];
            }
            Bv.sps[row][jj] = v;
        }
        __syncthreads();   // winw shared across units

        for (int idx = utid; idx < 7 * 64 + 4 * 64; idx += 256) {
            if (idx < 7 * 64) {
                int row = idx >> 6, d = idx & 63;
                float a = 0.f;
                #pragma unroll
                for (int k = 0; k < 32; k++) a = fmaf(Bv.sps[row][k], un.pb.winw[d][k], a);
                Bv.sxpre[row][d] = a;
            } else {
                int i2 = idx - 7 * 64;
                int row = i2 >> 6, d = i2 & 63;
                float a = 0.f;
                #pragma unroll
                for (int k = 0; k < 32; k++) a = fmaf(Bv.sps[row + 3][k], un.pb.winw[64 + d][k], a);
                g_gate[(base + row) * DI + d] = a;
            }
        }
        unit_bar(u);

        {   // conv + silu: 4 rows x 64 = 256
            int r = utid >> 6, d = utid & 63;
            float acc = un.pb.scb[d];
            #pragma unroll
            for (int kk = 0; kk < 4; kk++)
                acc = fmaf(Bv.sxpre[r + kk][d], un.pb.scwT[kk][d], acc);
            float xv = acc / (1.f + __expf(-acc));
            Bv.sx[r][d] = xv;
            g_x[(base + r) * DI + d] = xv;
        }
        unit_bar(u);

        if (utid < 136) {                       // x_proj: 4 rows x 34
            int r = utid / 34, jj = utid % 34;
            float a = 0.f;
            #pragma unroll
            for (int dd = 0; dd < 64; dd++) a = fmaf(Bv.sx[r][dd], xpw[jj * 64 + dd], a);
            Bv.xd[r][jj] = a;
            if (jj >= 18)      g_Cm[(base + r) * DS + (jj - 18)] = a;
            else if (jj >= 2)  g_Bm[(base + r) * DS + (jj - 2)]  = a;
        }
        unit_bar(u);

        {   // dt = softplus(...): 256
            int r = utid >> 6, d = utid & 63;
            float dtraw = fmaf(Bv.xd[r][0], un.pb.sdtw[d * 2],
                          fmaf(Bv.xd[r][1], un.pb.sdtw[d * 2 + 1], un.pb.sdtb[d]));
            float dtv = fmaxf(dtraw, 0.f) + log1pf(__expf(-fabsf(dtraw)));
            Bv.sdt[r][d] = dtv;
            g_dt[(base + r) * DI + d] = dtv;
        }
        unit_bar(u);

        // sub-chunk summaries (4 chains/thread) + 3-unit block summary
        {
            int d = utid >> 2;
            int n0 = (utid & 3) * 4;
            float4 al = *(const float4*)(A_log + d * DS + n0);
            float a0 = -__expf(al.x), a1 = -__expf(al.y);
            float a2 = -__expf(al.z), a3 = -__expf(al.w);
            float ra0 = 1.f, ra1 = 1.f, ra2 = 1.f, ra3 = 1.f;
            float rb0 = 0.f, rb1 = 0.f, rb2 = 0.f, rb3 = 0.f;
            #pragma unroll
            for (int t = 0; t < CT; t++) {
                float dtv = Bv.sdt[t][d];
                float dtx = dtv * Bv.sx[t][d];
                float dA0 = __expf(dtv * a0), dA1 = __expf(dtv * a1);
                float dA2 = __expf(dtv * a2), dA3 = __expf(dtv * a3);
                ra0 *= dA0; ra1 *= dA1; ra2 *= dA2; ra3 *= dA3;
                rb0 = fmaf(dA0, rb0, dtx * Bv.xd[t][2 + n0]);
                rb1 = fmaf(dA1, rb1, dtx * Bv.xd[t][3 + n0]);
                rb2 = fmaf(dA2, rb2, dtx * Bv.xd[t][4 + n0]);
                rb3 = fmaf(dA3, rb3, dtx * Bv.xd[t][5 + n0]);
            }
            size_t o = (size_t)c * CHAINS + b * 1024 + 4 * utid;
            *(float4*)(g_ca + o) = make_float4(ra0, ra1, ra2, ra3);
            *(float4*)(g_cb + o) = make_float4(rb0, rb1, rb2, rb3);

            // serial 3-unit combine -> block summary (block-wide syncs)
            if (u == 0) {
                *(float4*)(s_exA + 4 * utid) = make_float4(ra0, ra1, ra2, ra3);
                *(float4*)(s_exB + 4 * utid) = make_float4(rb0, rb1, rb2, rb3);
            }
            __syncthreads();
            if (u == 1) {
                float4 pa = *(const float4*)(s_exA + 4 * utid);
                float4 pb = *(const float4*)(s_exB + 4 * utid);
                float4 NA, NB;
                NA.x = ra0 * pa.x;  NB.x = fmaf(ra0, pb.x, rb0);
                NA.y = ra1 * pa.y;  NB.y = fmaf(ra1, pb.y, rb1);
                NA.z = ra2 * pa.z;  NB.z = fmaf(ra2, pb.z, rb2);
                NA.w = ra3 * pa.w;  NB.w = fmaf(ra3, pb.w, rb3);
                *(float4*)(s_exA + 4 * utid) = NA;
                *(float4*)(s_exB + 4 * utid) = NB;
            }
            __syncthreads();
            if (u == 2) {
                float4 pa = *(const float4*)(s_exA + 4 * utid);
                float4 pb = *(const float4*)(s_exB + 4 * utid);
                float4 NA, NB;
                NA.x = ra0 * pa.x;  NB.x = fmaf(ra0, pb.x, rb0);
                NA.y = ra1 * pa.y;  NB.y = fmaf(ra1, pb.y, rb1);
                NA.z = ra2 * pa.z;  NB.z = fmaf(ra2, pb.z, rb2);
                NA.w = ra3 * pa.w;  NB.w = fmaf(ra3, pb.w, rb3);
                int blk = blockIdx.x % BLKB;
                size_t ob = (size_t)blk * CHAINS + b * 1024 + 4 * utid;
                *(float4*)(g_ba + ob) = NA;
                *(float4*)(g_bb + ob) = NB;
            }
        }
    }
    grid_barrier();   // #2: all ca/cb/ba/bb visible

    // =================== phase C: 2-level prefix + scan + gate + out_proj ==
    {
        PhaseC& C = un.pc.c[u];
        int cu = blockIdx.x * UNITS + u;
        int base = cu * 4;
        int b = base / LSEQ;
        int l0 = base % LSEQ;
        int c = l0 >> 2;
        int blk = blockIdx.x % BLKB;

        for (int idx = tid; idx < 2048; idx += 768)
            un.pc.sop[idx >> 6][idx & 63] = opw[idx];
        {
            int t = utid >> 6, dd = utid & 63;
            C.sx[t][dd]  = g_x[(base + t) * DI + dd];
            C.sg[t][dd]  = g_gate[(base + t) * DI + dd];
            C.sdt[t][dd] = g_dt[(base + t) * DI + dd];
        }
        if (utid < 64) {
            int t = utid >> 4, nn = utid & 15;
            C.sB[t][nn] = g_Bm[(base + t) * DS + nn];
            C.sC[t][nn] = g_Cm[(base + t) * DS + nn];
        }

        int d = utid >> 2;
        int n0 = (utid & 3) * 4;
        float4 al = *(const float4*)(A_log + 4 * utid);
        float a0 = -__expf(al.x), a1 = -__expf(al.y);
        float a2 = -__expf(al.z), a3 = -__expf(al.w);
        float h0 = 0.f, h1 = 0.f, h2 = 0.f, h3 = 0.f;
        {
            size_t gc = (size_t)b * 1024 + 4 * utid;
            #pragma unroll 4
            for (int bk = 0; bk < blk; bk++) {
                float4 av = *(const float4*)(g_ba + (size_t)bk * CHAINS + gc);
                float4 bv = *(const float4*)(g_bb + (size_t)bk * CHAINS + gc);
                h0 = fmaf(av.x, h0, bv.x);
                h1 = fmaf(av.y, h1, bv.y);
                h2 = fmaf(av.z, h2, bv.z);
                h3 = fmaf(av.w, h3, bv.w);
            }
            for (int cc2 = blk * UNITS; cc2 < c; cc2++) {
                float4 av = *(const float4*)(g_ca + (size_t)cc2 * CHAINS + gc);
                float4 bv = *(const float4*)(g_cb + (size_t)cc2 * CHAINS + gc);
                h0 = fmaf(av.x, h0, bv.x);
                h1 = fmaf(av.y, h1, bv.y);
                h2 = fmaf(av.z, h2, bv.z);
                h3 = fmaf(av.w, h3, bv.w);
            }
        }
        float Dv = Dp[d];
        __syncthreads();   // sop shared across units

        #pragma unroll
        for (int t = 0; t < CT; t++) {
            float dtv = C.sdt[t][d];
            float xv  = C.sx[t][d];
            float dtx = dtv * xv;
            float dA0 = __expf(dtv * a0), dA1 = __expf(dtv * a1);
            float dA2 = __expf(dtv * a2), dA3 = __expf(dtv * a3);
            h0 = fmaf(dA0, h0, dtx * C.sB[t][n0 + 0]);
            h1 = fmaf(dA1, h1, dtx * C.sB[t][n0 + 1]);
            h2 = fmaf(dA2, h2, dtx * C.sB[t][n0 + 2]);
            h3 = fmaf(dA3, h3, dtx * C.sB[t][n0 + 3]);
            float yp = h0 * C.sC[t][n0 + 0] + h1 * C.sC[t][n0 + 1]
                     + h2 * C.sC[t][n0 + 2] + h3 * C.sC[t][n0 + 3];
            yp += __shfl_xor_sync(0xffffffffu, yp, 1);
            yp += __shfl_xor_sync(0xffffffffu, yp, 2);
            if ((utid & 3) == 0) {
                float y = yp + xv * Dv;
                float g = C.sg[t][d];
                y *= g / (1.f + __expf(-g));
                C.ysm[t][d] = y;
            }
        }
        unit_bar(u);
        if (utid < CT * SOUT) {                 // 128 threads: 4 t x 32 f
            int t = utid >> 5, f = utid & 31;
            float acc = 0.f;
            #pragma unroll
            for (int dd = 0; dd < DI; dd++)
                acc = fmaf(C.ysm[t][dd], un.pc.sop[f][dd], acc);
            out[(size_t)(base + t) * SOUT + f] = acc;
        }
    }
}

// ---------------- K7: z_prime = z*zw + zb + outer(sp, sp) ------------------
// grid = B_ x 192 s-groups(4 rows) x 12 t-strips(64 t) = 4608 blocks; block 256.
__global__ void __launch_bounds__(256) k7_z(const float* __restrict__ z,
                                            const float* __restrict__ zw,
                                            const float* __restrict__ zbv,
                                            const float* __restrict__ sp,
                                            float* __restrict__ outz) {
    int blk = blockIdx.x;
    int b = blk / 2304;
    int rem = blk % 2304;
    int s0 = (rem / 12) * 4;
    int t0 = (rem % 12) * 64;
    int tx = threadIdx.x & 7;
    int tl = threadIdx.x >> 3;
    int tb = t0 + tl * 2;
    const float* zrow = z + (size_t)(b * LSEQ) * LSEQ;
    float* orow = outz + (size_t)(b * LSEQ) * LSEQ * ZF;

    float2 zq[4];
    #pragma unroll
    for (int si = 0; si < 4; si++)
        zq[si] = *(const float2*)(zrow + (size_t)(s0 + si) * LSEQ + tb);
    float4 sps[4];
    #pragma unroll
    for (int si = 0; si < 4; si++)
        sps[si] = ((const float4*)(sp + (size_t)(b * LSEQ + s0 + si) * SOUT))[tx];
    float4 spt0 = ((const float4*)(sp + (size_t)(b * LSEQ + tb) * SOUT))[tx];
    float4 spt1 = ((const float4*)(sp + (size_t)(b * LSEQ + tb + 1) * SOUT))[tx];
    float4 zw4 = ((const float4*)zw)[tx];
    float4 zb4 = ((const float4*)zbv)[tx];

    #pragma unroll
    for (int si = 0; si < 4; si++) {
        float zv0 = zq[si].x, zv1 = zq[si].y;
        float4 o0, o1;
        o0.x = fmaf(zv0, zw4.x, zb4.x) + sps[si].x * spt0.x;
        o0.y = fmaf(zv0, zw4.y, zb4.y) + sps[si].y * spt0.y;
        o0.z = fmaf(zv0, zw4.z, zb4.z) + sps[si].z * spt0.z;
        o0.w = fmaf(zv0, zw4.w, zb4.w) + sps[si].w * spt0.w;
        o1.x = fmaf(zv1, zw4.x, zb4.x) + sps[si].x * spt1.x;
        o1.y = fmaf(zv1, zw4.y, zb4.y) + sps[si].y * spt1.y;
        o1.z = fmaf(zv1, zw4.z, zb4.z) + sps[si].z * spt1.z;
        o1.w = fmaf(zv1, zw4.w, zb4.w) + sps[si].w * spt1.w;
        size_t rb_ = (size_t)(s0 + si) * LSEQ + tb;
        __stcs((float4*)(orow + rb_ * ZF + tx * 4), o0);
        __stcs((float4*)(orow + (rb_ + 1) * ZF + tx * 4), o1);
    }
}

// ---------------- launch ----------------------------------------------------
extern "C" void kernel_launch(void* const* d_in, const int* in_sizes, int n_in,
                              void* d_out, int out_size) {
    const float* s        = (const float*)d_in[0];
    const float* z        = (const float*)d_in[1];
    const float* s_proj_w = (const float*)d_in[2];
    const float* s_proj_b = (const float*)d_in[3];
    const float* z_proj_w = (const float*)d_in[4];
    const float* z_proj_b = (const float*)d_in[5];
    const float* in_proj_w= (const float*)d_in[6];
    const float* conv_w   = (const float*)d_in[7];
    const float* conv_b   = (const float*)d_in[8];
    const float* x_proj_w = (const float*)d_in[9];
    const float* dt_proj_w= (const float*)d_in[10];
    const float* dt_proj_b= (const float*)d_in[11];
    const float* A_log    = (const float*)d_in[12];
    const float* Dp       = (const float*)d_in[13];
    const float* out_proj_w = (const float*)d_in[14];

    float* out    = (float*)d_out;
    float* sp_out = out;                       // [2,768,32]
    float* z_out  = out + (size_t)B_ * LSEQ * SOUT;

    mamba_one<<<NBLK, 768>>>(s, s_proj_w, s_proj_b, in_proj_w, conv_w, conv_b,
                             x_proj_w, dt_proj_w, dt_proj_b, A_log, Dp,
                             out_proj_w, sp_out);
    k7_z<<<4608, 256>>>(z, z_proj_w, z_proj_b, sp_out, z_out);
}